// round 16
// baseline (speedup 1.0000x reference)
#include <cuda_runtime.h>
#include <cuda_fp16.h>
#include <math.h>
#include <stdint.h>

// Problem constants
#define NB 32
#define NT 4096
#define NH 256
#define ND 512
#define NBLK 64            // t-blocks per batch in scores (NT/64)

#define MBAR_CORR 0.62f    // E[sech^2(x)], x ~ N(0,1)

// Device scratch (allocation-free rule: __device__ globals)
__device__ __align__(16) __half g_wh[NH * ND];   // W_e as fp16
__device__ float g_hbias[NB * NH];               // h_proj + b_attn
__device__ float g_scores[NB * NT];
__device__ float g_ck[ND];                       // sum_h v_h * (W - fp16(W))
__device__ float g_gw[ND];                       // sum_h v_h * fp16(W)
__device__ float g_pm[NB * NBLK];                // per-block max
__device__ float g_pz[NB * NBLK];                // per-block sum exp
__device__ float g_M[NB];                        // global max per b
__device__ float g_invZ[NB];                     // global 1/Z per b
__device__ __align__(16) float g_pctx[NB * NBLK * ND];   // per-block partial ctx

// ---------------------------------------------------------------------------
// helpers
// ---------------------------------------------------------------------------
__device__ __forceinline__ uint32_t smem_u32(const void* p) {
    uint32_t a;
    asm("{ .reg .u64 t; cvta.to.shared.u64 t, %1; cvt.u32.u64 %0, t; }"
        : "=r"(a) : "l"(p));
    return a;
}
__device__ __forceinline__ void cp_async16(uint32_t dst, const void* src) {
    asm volatile("cp.async.ca.shared.global [%0], [%1], 16;"
                 :: "r"(dst), "l"(src) : "memory");
}
#define CP_COMMIT() asm volatile("cp.async.commit_group;" ::: "memory")
#define CP_WAIT0()  asm volatile("cp.async.wait_group 0;" ::: "memory")

// fast tanh: 1 - 2/(e^{2x}+1). Saturates correctly (e->inf => 1, e->0 => -1).
__device__ __forceinline__ float fast_tanh(float x) {
    float e = __expf(2.0f * x);
    return 1.0f - __fdividef(2.0f, e + 1.0f);
}

// ---------------------------------------------------------------------------
// Kernel 0: prep — grid (4 + NH) x 128 threads.
// blocks 0..3:   atomics-free W_e -> fp16 conversion + ck/gw functionals
// blocks 4..259: h_proj + b_attn (one block per h)
// ---------------------------------------------------------------------------
__global__ void prep_kernel(const float* __restrict__ hidden,
                            const float* __restrict__ W,
                            const float* __restrict__ b_attn,
                            const float* __restrict__ v) {
    int blk = blockIdx.x;
    int tid = threadIdx.x;

    if (blk < 4) {
        __shared__ float sv[NH];
        for (int i = tid; i < NH; i += 128) sv[i] = v[i];
        __syncthreads();
        int d = blk * 128 + tid;
        float ck = 0.f, gw = 0.f;
        #pragma unroll 4
        for (int h = 0; h < NH; h++) {
            float w = W[h * 1024 + 512 + d];
            __half wh = __float2half_rn(w);
            g_wh[h * ND + d] = wh;
            float whf = __half2float(wh);
            ck += sv[h] * (w - whf);
            gw += sv[h] * whf;
        }
        g_ck[d] = ck;
        g_gw[d] = gw;
    } else {
        int h = blk - 4;
        const float* Wrow = W + h * 1024;
        int warp = tid >> 5, lane = tid & 31;
        for (int b = warp; b < NB; b += 4) {
            float s = 0.f;
            for (int d = lane; d < ND; d += 32)
                s += hidden[b * ND + d] * Wrow[d];
            #pragma unroll
            for (int o = 16; o; o >>= 1) s += __shfl_xor_sync(0xFFFFFFFFu, s, o);
            if (lane == 0) g_hbias[b * NH + h] = s + b_attn[h];
        }
    }
}

// ---------------------------------------------------------------------------
// Kernel 1: fp16 GEMM (LDS fragments, bias-in-acc) + quant correction
// + fast-tanh/v-dot + split-softmax partial context. grid: (NT/64, NB), 256t.
// ---------------------------------------------------------------------------
#define PAD 72   // 144B rows: 16B-aligned

#define MMA_F16(d, a, bb)                                                      \
    asm volatile(                                                              \
        "mma.sync.aligned.m16n8k16.row.col.f32.f16.f16.f32 "                   \
        "{%0,%1,%2,%3},{%4,%5,%6,%7},{%8,%9},{%0,%1,%2,%3};"                   \
        : "+f"(d[0]), "+f"(d[1]), "+f"(d[2]), "+f"(d[3])                       \
        : "r"(a[0]), "r"(a[1]), "r"(a[2]), "r"(a[3]), "r"(bb[0]), "r"(bb[1]))

__global__ __launch_bounds__(256, 2) void scores_kernel(
    const float* __restrict__ enc, const float* __restrict__ v) {
    __shared__ __align__(16) __half As[2][64][PAD];
    __shared__ __align__(16) __half Bs[2][256][PAD];
    __shared__ float shGW[ND], shCK[ND];
    __shared__ float rowcorr[64];
    __shared__ float sfin[64], swgt[64];
    __shared__ float smb[1];

    int b = blockIdx.y;
    int blkx = blockIdx.x;
    int t0 = blkx * 64;
    int tid = threadIdx.x;
    int lane = tid & 31;
    int warp = tid >> 5;
    int wm = warp >> 2;   // 0..1
    int wn = warp & 3;    // 0..3

    for (int i = tid; i < ND; i += 256) { shGW[i] = g_gw[i]; shCK[i] = g_ck[i]; }

    // accumulators initialized with hbias (bias folded into MMA C)
    float acc[2][8][4];
    {
        int hb_h = wn * 64 + 2 * (lane & 3);
        #pragma unroll
        for (int ni = 0; ni < 8; ni++) {
            float hb0 = g_hbias[b * NH + hb_h + ni * 8];
            float hb1 = g_hbias[b * NH + hb_h + ni * 8 + 1];
            #pragma unroll
            for (int mi = 0; mi < 2; mi++) {
                acc[mi][ni][0] = hb0; acc[mi][ni][1] = hb1;
                acc[mi][ni][2] = hb0; acc[mi][ni][3] = hb1;
            }
        }
    }

    const float* Abase = enc + ((size_t)(b * NT + t0)) * ND;

    const int arow = tid >> 2;
    const int acg = tid & 3;
    const float* asrc = Abase + arow * ND + acg * 16;

    int brow[8], bc8[8];
    #pragma unroll
    for (int i = 0; i < 8; i++) {
        int idx = tid + i * 256;
        brow[i] = idx >> 3;
        bc8[i]  = idx & 7;
    }

    float corrA = 0.f, corrW = 0.f;

    // ---- prologue: B0 via cp.async; A0 convert+store (+corr) ----
    #pragma unroll
    for (int i = 0; i < 8; i++)
        cp_async16(smem_u32(&Bs[0][brow[i]][bc8[i] * 8]),
                   g_wh + brow[i] * ND + bc8[i] * 8);
    CP_COMMIT();
    {
        float xv[16];
        #pragma unroll
        for (int q = 0; q < 4; q++) {
            float4 x = *(const float4*)(asrc + q * 4);
            xv[q * 4] = x.x; xv[q * 4 + 1] = x.y;
            xv[q * 4 + 2] = x.z; xv[q * 4 + 3] = x.w;
        }
        __half hv[16];
        int kb = acg * 16;
        #pragma unroll
        for (int j = 0; j < 16; j++) {
            hv[j] = __float2half_rn(xv[j]);
            float hf = __half2float(hv[j]);
            corrA += (xv[j] - hf) * shGW[kb + j];
            corrW += xv[j] * shCK[kb + j];
        }
        #pragma unroll
        for (int q = 0; q < 2; q++) {
            uint4 pk;
            __half2 q0 = __halves2half2(hv[q*8+0], hv[q*8+1]);
            __half2 q1 = __halves2half2(hv[q*8+2], hv[q*8+3]);
            __half2 q2 = __halves2half2(hv[q*8+4], hv[q*8+5]);
            __half2 q3 = __halves2half2(hv[q*8+6], hv[q*8+7]);
            pk.x = *(uint32_t*)&q0; pk.y = *(uint32_t*)&q1;
            pk.z = *(uint32_t*)&q2; pk.w = *(uint32_t*)&q3;
            *(uint4*)&As[0][arow][acg * 16 + q * 8] = pk;
        }
    }
    CP_WAIT0();
    __syncthreads();

    for (int c = 0; c < 8; c++) {
        const int s = c & 1;

        float xv[16];
        if (c < 7) {
            const float* nsrc = asrc + (c + 1) * 64;
            #pragma unroll
            for (int q = 0; q < 4; q++) {
                float4 x = *(const float4*)(nsrc + q * 4);
                xv[q * 4] = x.x; xv[q * 4 + 1] = x.y;
                xv[q * 4 + 2] = x.z; xv[q * 4 + 3] = x.w;
            }
            #pragma unroll
            for (int i = 0; i < 8; i++)
                cp_async16(smem_u32(&Bs[s ^ 1][brow[i]][bc8[i] * 8]),
                           g_wh + brow[i] * ND + (c + 1) * 64 + bc8[i] * 8);
            CP_COMMIT();
        }

        // ---- compute chunk c (plain LDS fragment loads) ----
        #pragma unroll
        for (int kx = 0; kx < 4; kx++) {
            const int kk = kx * 16;
            uint32_t ah[2][4], bh[8][2];
            int cw = kk + 2 * (lane & 3);
            int rq = lane >> 2;
            #pragma unroll
            for (int mi = 0; mi < 2; mi++) {
                int r = wm * 32 + mi * 16 + rq;
                ah[mi][0] = *(const uint32_t*)&As[s][r][cw];
                ah[mi][1] = *(const uint32_t*)&As[s][r + 8][cw];
                ah[mi][2] = *(const uint32_t*)&As[s][r][cw + 8];
                ah[mi][3] = *(const uint32_t*)&As[s][r + 8][cw + 8];
            }
            #pragma unroll
            for (int ni = 0; ni < 8; ni++) {
                int n = wn * 64 + ni * 8 + rq;
                bh[ni][0] = *(const uint32_t*)&Bs[s][n][cw];
                bh[ni][1] = *(const uint32_t*)&Bs[s][n][cw + 8];
            }
            #pragma unroll
            for (int mi = 0; mi < 2; mi++)
                #pragma unroll
                for (int ni = 0; ni < 8; ni++)
                    MMA_F16(acc[mi][ni], ah[mi], bh[ni]);
        }

        if (c < 7) {
            __half hv[16];
            int kb = (c + 1) * 64 + acg * 16;
            #pragma unroll
            for (int j = 0; j < 16; j++) {
                hv[j] = __float2half_rn(xv[j]);
                float hf = __half2float(hv[j]);
                corrA += (xv[j] - hf) * shGW[kb + j];
                corrW += xv[j] * shCK[kb + j];
            }
            #pragma unroll
            for (int q = 0; q < 2; q++) {
                uint4 pk;
                __half2 q0 = __halves2half2(hv[q*8+0], hv[q*8+1]);
                __half2 q1 = __halves2half2(hv[q*8+2], hv[q*8+3]);
                __half2 q2 = __halves2half2(hv[q*8+4], hv[q*8+5]);
                __half2 q3 = __halves2half2(hv[q*8+6], hv[q*8+7]);
                pk.x = *(uint32_t*)&q0; pk.y = *(uint32_t*)&q1;
                pk.z = *(uint32_t*)&q2; pk.w = *(uint32_t*)&q3;
                *(uint4*)&As[s ^ 1][arow][acg * 16 + q * 8] = pk;
            }
            CP_WAIT0();
        }
        __syncthreads();
    }

    // ---- per-row quantization correction ----
    {
        float corr = MBAR_CORR * (corrA + corrW);
        corr += __shfl_down_sync(0xFFFFFFFFu, corr, 1);
        corr += __shfl_down_sync(0xFFFFFFFFu, corr, 2);
        if ((tid & 3) == 0) rowcorr[arow] = corr;
    }

    // ---- epilogue: fast_tanh(acc) . v  (bias already in acc) ----
    float* ssc = (float*)&As[0][0][0];
    float vr0[8], vr1[8];
    {
        int h = wn * 64 + 2 * (lane & 3);
        #pragma unroll
        for (int ni = 0; ni < 8; ni++) {
            vr0[ni] = v[h + ni * 8];
            vr1[ni] = v[h + ni * 8 + 1];
        }
    }
    float p[2][2] = {{0.f, 0.f}, {0.f, 0.f}};
    #pragma unroll
    for (int mi = 0; mi < 2; mi++)
        #pragma unroll
        for (int ni = 0; ni < 8; ni++) {
            p[mi][0] += fast_tanh(acc[mi][ni][0]) * vr0[ni]
                      + fast_tanh(acc[mi][ni][1]) * vr1[ni];
            p[mi][1] += fast_tanh(acc[mi][ni][2]) * vr0[ni]
                      + fast_tanh(acc[mi][ni][3]) * vr1[ni];
        }
    #pragma unroll
    for (int mi = 0; mi < 2; mi++)
        #pragma unroll
        for (int hf = 0; hf < 2; hf++) {
            float s = p[mi][hf];
            s += __shfl_xor_sync(0xFFFFFFFFu, s, 1);
            s += __shfl_xor_sync(0xFFFFFFFFu, s, 2);
            if ((lane & 3) == 0)
                ssc[(wm * 32 + mi * 16 + hf * 8 + (lane >> 2)) * 4 + wn] = s;
        }
    __syncthreads();
    if (tid < 64) {
        float s = ssc[tid * 4] + ssc[tid * 4 + 1] + ssc[tid * 4 + 2] + ssc[tid * 4 + 3]
                + rowcorr[tid];
        g_scores[b * NT + t0 + tid] = s;
        sfin[tid] = s;
    }
    __syncthreads();

    // ---- block-local softmax stats ----
    if (tid < 32) {
        float m = fmaxf(sfin[tid], sfin[tid + 32]);
        #pragma unroll
        for (int o = 16; o; o >>= 1) m = fmaxf(m, __shfl_xor_sync(0xFFFFFFFFu, m, o));
        if (tid == 0) smb[0] = m;
    }
    __syncthreads();
    float mb = smb[0];
    if (tid < 64) swgt[tid] = __expf(sfin[tid] - mb);
    __syncthreads();
    if (tid < 32) {
        float z = swgt[tid] + swgt[tid + 32];
        #pragma unroll
        for (int o = 16; o; o >>= 1) z += __shfl_xor_sync(0xFFFFFFFFu, z, o);
        if (tid == 0) { g_pm[b * NBLK + blkx] = mb; g_pz[b * NBLK + blkx] = z; }
    }

    // ---- partial context: pctx[d] = sum_t w_t * enc[t,d] (tile is L2-hot) ----
    {
        int d0 = tid * 2;
        const float* ep = Abase + d0;
        float a0 = 0.f, a1 = 0.f;
        #pragma unroll 8
        for (int r = 0; r < 64; r++) {
            float2 x = *(const float2*)(ep + (size_t)r * ND);
            float wt = swgt[r];
            a0 += wt * x.x; a1 += wt * x.y;
        }
        float* dst = g_pctx + ((size_t)(b * NBLK + blkx)) * ND + d0;
        dst[0] = a0; dst[1] = a1;
    }
}

// ---------------------------------------------------------------------------
// Kernel 2: per-b global softmax stats M, 1/Z. grid: NB, 64 threads
// ---------------------------------------------------------------------------
__global__ void mz_kernel() {
    __shared__ float rm[NBLK], rz[NBLK], sM[1];
    int b = blockIdx.x, t = threadIdx.x;
    rm[t] = g_pm[b * NBLK + t];
    rz[t] = g_pz[b * NBLK + t];
    __syncthreads();
    if (t < 32) {
        float m = fmaxf(rm[t], rm[t + 32]);
        #pragma unroll
        for (int o = 16; o; o >>= 1) m = fmaxf(m, __shfl_xor_sync(0xFFFFFFFFu, m, o));
        if (t == 0) sM[0] = m;
    }
    __syncthreads();
    float M = sM[0];
    if (t < 32) {
        float z = __expf(rm[t] - M) * rz[t] + __expf(rm[t + 32] - M) * rz[t + 32];
        #pragma unroll
        for (int o = 16; o; o >>= 1) z += __shfl_xor_sync(0xFFFFFFFFu, z, o);
        if (t == 0) { g_M[b] = M; g_invZ[b] = 1.0f / z; }
    }
}

// ---------------------------------------------------------------------------
// Kernel 3: finalize. grid: (9, NB), 512 thr. x=0: ctx; x=1..8: attn chunks
// ---------------------------------------------------------------------------
__global__ __launch_bounds__(512) void finalize_kernel(
    float* __restrict__ attn, float* __restrict__ ctx) {
    int b = blockIdx.y, part = blockIdx.x, tid = threadIdx.x;
    float M = g_M[b], invZ = g_invZ[b];

    if (part == 0) {
        __shared__ float sef[NBLK];
        if (tid < NBLK) sef[tid] = __expf(g_pm[b * NBLK + tid] - M);
        __syncthreads();
        float a = 0.f;
        const float* pc = g_pctx + ((size_t)b * NBLK) * ND + tid;
        #pragma unroll 8
        for (int k = 0; k < NBLK; k++)
            a += sef[k] * pc[(size_t)k * ND];
        ctx[b * ND + tid] = a * invZ;
    } else {
        int t = (part - 1) * 512 + tid;
        attn[b * NT + t] = __expf(g_scores[b * NT + t] - M) * invZ;
    }
}

// ---------------------------------------------------------------------------
extern "C" void kernel_launch(void* const* d_in, const int* in_sizes, int n_in,
                              void* d_out, int out_size) {
    const float* hidden = (const float*)d_in[0];
    const float* enc    = (const float*)d_in[1];
    const float* W      = (const float*)d_in[2];
    const float* b_attn = (const float*)d_in[3];
    const float* v      = (const float*)d_in[4];

    float* out  = (float*)d_out;
    float* ctx  = out;                 // (32, 512)
    float* attn = out + NB * ND;       // (32, 4096)

    prep_kernel<<<4 + NH, 128>>>(hidden, W, b_attn, v);
    scores_kernel<<<dim3(NT / 64, NB), 256>>>(enc, v);
    mz_kernel<<<NB, NBLK>>>();
    finalize_kernel<<<dim3(9, NB), 512>>>(attn, ctx);
}

// round 17
// speedup vs baseline: 1.1165x; 1.1165x over previous
#include <cuda_runtime.h>
#include <cuda_fp16.h>
#include <math.h>
#include <stdint.h>

// Problem constants
#define NB 32
#define NT 4096
#define NH 256
#define ND 512
#define NBLK 64            // t-blocks per batch in scores (NT/64)

#define MBAR_CORR 0.62f    // E[sech^2(x)], x ~ N(0,1)

// Device scratch (allocation-free rule: __device__ globals)
__device__ __align__(16) __half g_wh[NH * ND];   // W_e as fp16
__device__ float g_hbias[NB * NH];               // h_proj + b_attn
__device__ float g_scores[NB * NT];
__device__ float g_ck[ND];                       // sum_h v_h * (W - fp16(W))
__device__ float g_gw[ND];                       // sum_h v_h * fp16(W)
__device__ float g_pm[NB * NBLK];                // per-block max
__device__ float g_pz[NB * NBLK];                // per-block sum exp
__device__ __align__(16) float g_pctx[NB * NBLK * ND];   // per-block partial ctx

// ---------------------------------------------------------------------------
// helpers
// ---------------------------------------------------------------------------
__device__ __forceinline__ uint32_t smem_u32(const void* p) {
    uint32_t a;
    asm("{ .reg .u64 t; cvta.to.shared.u64 t, %1; cvt.u32.u64 %0, t; }"
        : "=r"(a) : "l"(p));
    return a;
}
__device__ __forceinline__ void cp_async16(uint32_t dst, const void* src) {
    asm volatile("cp.async.ca.shared.global [%0], [%1], 16;"
                 :: "r"(dst), "l"(src) : "memory");
}
#define CP_COMMIT() asm volatile("cp.async.commit_group;" ::: "memory")
#define CP_WAIT0()  asm volatile("cp.async.wait_group 0;" ::: "memory")

// fast tanh: 1 - 2/(e^{2x}+1). Saturates correctly (e->inf => 1, e->0 => -1).
__device__ __forceinline__ float fast_tanh(float x) {
    float e = __expf(2.0f * x);
    return 1.0f - __fdividef(2.0f, e + 1.0f);
}

// ---------------------------------------------------------------------------
// Kernel -1: zero the correction accumulators (graph-replay safe)
// ---------------------------------------------------------------------------
__global__ void zero_kernel() {
    g_ck[threadIdx.x] = 0.f;
    g_gw[threadIdx.x] = 0.f;
}

// ---------------------------------------------------------------------------
// Kernel 0: prep — W_e -> fp16 (+ error functionals), h_proj + b_attn
// (R15 form: one block per h, coalesced, atomics for ck/gw)
// ---------------------------------------------------------------------------
__global__ void prep_kernel(const float* __restrict__ hidden,
                            const float* __restrict__ W,
                            const float* __restrict__ b_attn,
                            const float* __restrict__ v) {
    int h = blockIdx.x;
    const float* Wrow = W + h * 1024;
    float vh = v[h];

    for (int d = threadIdx.x; d < ND; d += 128) {
        float w = Wrow[512 + d];
        __half wh = __float2half_rn(w);
        g_wh[h * ND + d] = wh;
        float whf = __half2float(wh);
        atomicAdd(&g_ck[d], vh * (w - whf));
        atomicAdd(&g_gw[d], vh * whf);
    }

    int warp = threadIdx.x >> 5, lane = threadIdx.x & 31;
    for (int b = warp; b < NB; b += 4) {
        float s = 0.f;
        for (int d = lane; d < ND; d += 32)
            s += hidden[b * ND + d] * Wrow[d];
        #pragma unroll
        for (int o = 16; o; o >>= 1) s += __shfl_xor_sync(0xFFFFFFFFu, s, o);
        if (lane == 0) g_hbias[b * NH + h] = s + b_attn[h];
    }
}

// ---------------------------------------------------------------------------
// Kernel 1: fp16 GEMM (LDS fragments, bias-in-acc) + quant correction
// + fast-tanh/v-dot + split-softmax partial context. grid: (NT/64, NB), 256t.
// ---------------------------------------------------------------------------
#define PAD 72   // 144B rows: 16B-aligned

#define MMA_F16(d, a, bb)                                                      \
    asm volatile(                                                              \
        "mma.sync.aligned.m16n8k16.row.col.f32.f16.f16.f32 "                   \
        "{%0,%1,%2,%3},{%4,%5,%6,%7},{%8,%9},{%0,%1,%2,%3};"                   \
        : "+f"(d[0]), "+f"(d[1]), "+f"(d[2]), "+f"(d[3])                       \
        : "r"(a[0]), "r"(a[1]), "r"(a[2]), "r"(a[3]), "r"(bb[0]), "r"(bb[1]))

__global__ __launch_bounds__(256, 2) void scores_kernel(
    const float* __restrict__ enc, const float* __restrict__ v) {
    __shared__ __align__(16) __half As[2][64][PAD];
    __shared__ __align__(16) __half Bs[2][256][PAD];
    __shared__ float shGW[ND], shCK[ND];
    __shared__ float rowcorr[64];
    __shared__ float sfin[64], swgt[64];
    __shared__ float smb[1];

    int b = blockIdx.y;
    int blkx = blockIdx.x;
    int t0 = blkx * 64;
    int tid = threadIdx.x;
    int lane = tid & 31;
    int warp = tid >> 5;
    int wm = warp >> 2;   // 0..1
    int wn = warp & 3;    // 0..3

    for (int i = tid; i < ND; i += 256) { shGW[i] = g_gw[i]; shCK[i] = g_ck[i]; }

    // accumulators initialized with hbias (bias folded into MMA C)
    float acc[2][8][4];
    {
        int hb_h = wn * 64 + 2 * (lane & 3);
        #pragma unroll
        for (int ni = 0; ni < 8; ni++) {
            float hb0 = g_hbias[b * NH + hb_h + ni * 8];
            float hb1 = g_hbias[b * NH + hb_h + ni * 8 + 1];
            #pragma unroll
            for (int mi = 0; mi < 2; mi++) {
                acc[mi][ni][0] = hb0; acc[mi][ni][1] = hb1;
                acc[mi][ni][2] = hb0; acc[mi][ni][3] = hb1;
            }
        }
    }

    const float* Abase = enc + ((size_t)(b * NT + t0)) * ND;

    const int arow = tid >> 2;
    const int acg = tid & 3;
    const float* asrc = Abase + arow * ND + acg * 16;

    int brow[8], bc8[8];
    #pragma unroll
    for (int i = 0; i < 8; i++) {
        int idx = tid + i * 256;
        brow[i] = idx >> 3;
        bc8[i]  = idx & 7;
    }

    float corrA = 0.f, corrW = 0.f;

    // ---- prologue: B0 via cp.async; A0 convert+store (+corr) ----
    #pragma unroll
    for (int i = 0; i < 8; i++)
        cp_async16(smem_u32(&Bs[0][brow[i]][bc8[i] * 8]),
                   g_wh + brow[i] * ND + bc8[i] * 8);
    CP_COMMIT();
    {
        float xv[16];
        #pragma unroll
        for (int q = 0; q < 4; q++) {
            float4 x = *(const float4*)(asrc + q * 4);
            xv[q * 4] = x.x; xv[q * 4 + 1] = x.y;
            xv[q * 4 + 2] = x.z; xv[q * 4 + 3] = x.w;
        }
        __half hv[16];
        int kb = acg * 16;
        #pragma unroll
        for (int j = 0; j < 16; j++) {
            hv[j] = __float2half_rn(xv[j]);
            float hf = __half2float(hv[j]);
            corrA += (xv[j] - hf) * shGW[kb + j];
            corrW += xv[j] * shCK[kb + j];
        }
        #pragma unroll
        for (int q = 0; q < 2; q++) {
            uint4 pk;
            __half2 q0 = __halves2half2(hv[q*8+0], hv[q*8+1]);
            __half2 q1 = __halves2half2(hv[q*8+2], hv[q*8+3]);
            __half2 q2 = __halves2half2(hv[q*8+4], hv[q*8+5]);
            __half2 q3 = __halves2half2(hv[q*8+6], hv[q*8+7]);
            pk.x = *(uint32_t*)&q0; pk.y = *(uint32_t*)&q1;
            pk.z = *(uint32_t*)&q2; pk.w = *(uint32_t*)&q3;
            *(uint4*)&As[0][arow][acg * 16 + q * 8] = pk;
        }
    }
    CP_WAIT0();
    __syncthreads();

    for (int c = 0; c < 8; c++) {
        const int s = c & 1;

        float xv[16];
        if (c < 7) {
            const float* nsrc = asrc + (c + 1) * 64;
            #pragma unroll
            for (int q = 0; q < 4; q++) {
                float4 x = *(const float4*)(nsrc + q * 4);
                xv[q * 4] = x.x; xv[q * 4 + 1] = x.y;
                xv[q * 4 + 2] = x.z; xv[q * 4 + 3] = x.w;
            }
            #pragma unroll
            for (int i = 0; i < 8; i++)
                cp_async16(smem_u32(&Bs[s ^ 1][brow[i]][bc8[i] * 8]),
                           g_wh + brow[i] * ND + (c + 1) * 64 + bc8[i] * 8);
            CP_COMMIT();
        }

        // ---- compute chunk c (plain LDS fragment loads) ----
        #pragma unroll
        for (int kx = 0; kx < 4; kx++) {
            const int kk = kx * 16;
            uint32_t ah[2][4], bh[8][2];
            int cw = kk + 2 * (lane & 3);
            int rq = lane >> 2;
            #pragma unroll
            for (int mi = 0; mi < 2; mi++) {
                int r = wm * 32 + mi * 16 + rq;
                ah[mi][0] = *(const uint32_t*)&As[s][r][cw];
                ah[mi][1] = *(const uint32_t*)&As[s][r + 8][cw];
                ah[mi][2] = *(const uint32_t*)&As[s][r][cw + 8];
                ah[mi][3] = *(const uint32_t*)&As[s][r + 8][cw + 8];
            }
            #pragma unroll
            for (int ni = 0; ni < 8; ni++) {
                int n = wn * 64 + ni * 8 + rq;
                bh[ni][0] = *(const uint32_t*)&Bs[s][n][cw];
                bh[ni][1] = *(const uint32_t*)&Bs[s][n][cw + 8];
            }
            #pragma unroll
            for (int mi = 0; mi < 2; mi++)
                #pragma unroll
                for (int ni = 0; ni < 8; ni++)
                    MMA_F16(acc[mi][ni], ah[mi], bh[ni]);
        }

        if (c < 7) {
            __half hv[16];
            int kb = (c + 1) * 64 + acg * 16;
            #pragma unroll
            for (int j = 0; j < 16; j++) {
                hv[j] = __float2half_rn(xv[j]);
                float hf = __half2float(hv[j]);
                corrA += (xv[j] - hf) * shGW[kb + j];
                corrW += xv[j] * shCK[kb + j];
            }
            #pragma unroll
            for (int q = 0; q < 2; q++) {
                uint4 pk;
                __half2 q0 = __halves2half2(hv[q*8+0], hv[q*8+1]);
                __half2 q1 = __halves2half2(hv[q*8+2], hv[q*8+3]);
                __half2 q2 = __halves2half2(hv[q*8+4], hv[q*8+5]);
                __half2 q3 = __halves2half2(hv[q*8+6], hv[q*8+7]);
                pk.x = *(uint32_t*)&q0; pk.y = *(uint32_t*)&q1;
                pk.z = *(uint32_t*)&q2; pk.w = *(uint32_t*)&q3;
                *(uint4*)&As[s ^ 1][arow][acg * 16 + q * 8] = pk;
            }
            CP_WAIT0();
        }
        __syncthreads();
    }

    // ---- per-row quantization correction ----
    {
        float corr = MBAR_CORR * (corrA + corrW);
        corr += __shfl_down_sync(0xFFFFFFFFu, corr, 1);
        corr += __shfl_down_sync(0xFFFFFFFFu, corr, 2);
        if ((tid & 3) == 0) rowcorr[arow] = corr;
    }

    // ---- epilogue: fast_tanh(acc) . v  (bias already in acc) ----
    float* ssc = (float*)&As[0][0][0];
    float vr0[8], vr1[8];
    {
        int h = wn * 64 + 2 * (lane & 3);
        #pragma unroll
        for (int ni = 0; ni < 8; ni++) {
            vr0[ni] = v[h + ni * 8];
            vr1[ni] = v[h + ni * 8 + 1];
        }
    }
    float p[2][2] = {{0.f, 0.f}, {0.f, 0.f}};
    #pragma unroll
    for (int mi = 0; mi < 2; mi++)
        #pragma unroll
        for (int ni = 0; ni < 8; ni++) {
            p[mi][0] += fast_tanh(acc[mi][ni][0]) * vr0[ni]
                      + fast_tanh(acc[mi][ni][1]) * vr1[ni];
            p[mi][1] += fast_tanh(acc[mi][ni][2]) * vr0[ni]
                      + fast_tanh(acc[mi][ni][3]) * vr1[ni];
        }
    #pragma unroll
    for (int mi = 0; mi < 2; mi++)
        #pragma unroll
        for (int hf = 0; hf < 2; hf++) {
            float s = p[mi][hf];
            s += __shfl_xor_sync(0xFFFFFFFFu, s, 1);
            s += __shfl_xor_sync(0xFFFFFFFFu, s, 2);
            if ((lane & 3) == 0)
                ssc[(wm * 32 + mi * 16 + hf * 8 + (lane >> 2)) * 4 + wn] = s;
        }
    __syncthreads();
    if (tid < 64) {
        float s = ssc[tid * 4] + ssc[tid * 4 + 1] + ssc[tid * 4 + 2] + ssc[tid * 4 + 3]
                + rowcorr[tid];
        g_scores[b * NT + t0 + tid] = s;
        sfin[tid] = s;
    }
    __syncthreads();

    // ---- block-local softmax stats ----
    if (tid < 32) {
        float m = fmaxf(sfin[tid], sfin[tid + 32]);
        #pragma unroll
        for (int o = 16; o; o >>= 1) m = fmaxf(m, __shfl_xor_sync(0xFFFFFFFFu, m, o));
        if (tid == 0) smb[0] = m;
    }
    __syncthreads();
    float mb = smb[0];
    if (tid < 64) swgt[tid] = __expf(sfin[tid] - mb);
    __syncthreads();
    if (tid < 32) {
        float z = swgt[tid] + swgt[tid + 32];
        #pragma unroll
        for (int o = 16; o; o >>= 1) z += __shfl_xor_sync(0xFFFFFFFFu, z, o);
        if (tid == 0) { g_pm[b * NBLK + blkx] = mb; g_pz[b * NBLK + blkx] = z; }
    }

    // ---- partial context: pctx[d] = sum_t w_t * enc[t,d] (tile is L2-hot) ----
    {
        int d0 = tid * 2;
        const float* ep = Abase + d0;
        float a0 = 0.f, a1 = 0.f;
        #pragma unroll 8
        for (int r = 0; r < 64; r++) {
            float2 x = *(const float2*)(ep + (size_t)r * ND);
            float wt = swgt[r];
            a0 += wt * x.x; a1 += wt * x.y;
        }
        float* dst = g_pctx + ((size_t)(b * NBLK + blkx)) * ND + d0;
        dst[0] = a0; dst[1] = a1;
    }
}

// ---------------------------------------------------------------------------
// Kernel 2: finalize. grid: (9, NB), 512 thr. Each block recomputes M, 1/Z
// from per-block stats (parallel reduction). x=0: ctx; x=1..8: attn chunks
// ---------------------------------------------------------------------------
__global__ __launch_bounds__(512) void finalize_kernel(
    float* __restrict__ attn, float* __restrict__ ctx) {
    __shared__ float sm[NBLK], sz[NBLK], sMZ[2];
    int b = blockIdx.y, part = blockIdx.x, tid = threadIdx.x;

    if (tid < NBLK) {
        sm[tid] = g_pm[b * NBLK + tid];
        sz[tid] = g_pz[b * NBLK + tid];
    }
    __syncthreads();
    if (tid < 32) {
        float m = fmaxf(sm[tid], sm[tid + 32]);
        #pragma unroll
        for (int o = 16; o; o >>= 1) m = fmaxf(m, __shfl_xor_sync(0xFFFFFFFFu, m, o));
        // broadcast m within warp, then sum z terms
        float z = __expf(sm[tid] - m) * sz[tid] + __expf(sm[tid + 32] - m) * sz[tid + 32];
        #pragma unroll
        for (int o = 16; o; o >>= 1) z += __shfl_xor_sync(0xFFFFFFFFu, z, o);
        if (tid == 0) { sMZ[0] = m; sMZ[1] = 1.0f / z; }
    }
    __syncthreads();
    float M = sMZ[0], invZ = sMZ[1];

    if (part == 0) {
        __shared__ float sef[NBLK];
        if (tid < NBLK) sef[tid] = __expf(sm[tid] - M);
        __syncthreads();
        float a = 0.f;
        const float* pc = g_pctx + ((size_t)b * NBLK) * ND + tid;
        #pragma unroll 8
        for (int k = 0; k < NBLK; k++)
            a += sef[k] * pc[(size_t)k * ND];
        ctx[b * ND + tid] = a * invZ;
    } else {
        int t = (part - 1) * 512 + tid;
        attn[b * NT + t] = __expf(g_scores[b * NT + t] - M) * invZ;
    }
}

// ---------------------------------------------------------------------------
extern "C" void kernel_launch(void* const* d_in, const int* in_sizes, int n_in,
                              void* d_out, int out_size) {
    const float* hidden = (const float*)d_in[0];
    const float* enc    = (const float*)d_in[1];
    const float* W      = (const float*)d_in[2];
    const float* b_attn = (const float*)d_in[3];
    const float* v      = (const float*)d_in[4];

    float* out  = (float*)d_out;
    float* ctx  = out;                 // (32, 512)
    float* attn = out + NB * ND;       // (32, 4096)

    zero_kernel<<<1, ND>>>();
    prep_kernel<<<NH, 128>>>(hidden, W, b_attn, v);
    scores_kernel<<<dim3(NT / 64, NB), 256>>>(enc, v);
    finalize_kernel<<<dim3(9, NB), 512>>>(attn, ctx);
}